// round 15
// baseline (speedup 1.0000x reference)
#include <cuda_runtime.h>
#include <cstdint>

// Aggregator: masked mean of sampled neighbor features.
//  d_in[0] features:      [N, 128] float32
//  d_in[1] neighbor_idx:  [N, 16]  int32
//  d_in[2] neighbor_mask: [N, 16]  int32 (0/1)
//  d_out   out:           [N, 128] float32
//
// Champion body (47.1us) unchanged, wrapped in a PERSISTENT grid-stride
// loop: 1036 blocks (148 SMs x 7 blocks x 8 warps = full 56-warp/SM
// residency at 36 regs). Removes the block-churn achieved-occupancy
// deficit (58.6% vs 87.5% theoretical) that the 12500-tiny-block launch
// pays at every wave transition; consecutive loop iterations also overlap
// node t+1 idx loads with node t tail gathers for free.

#define S 16
#define D 128
#define NBLOCKS (148 * 7)   // 7 blocks/SM x 8 warps = 56 warps/SM (reg ceiling)

__device__ __forceinline__ unsigned long long addx2(unsigned long long a, unsigned long long b) {
    unsigned long long r;
    asm("add.rn.f32x2 %0, %1, %2;" : "=l"(r) : "l"(a), "l"(b));
    return r;
}

__global__ __launch_bounds__(256) void agg_kernel(
    const float* __restrict__ feat,
    const int* __restrict__ nidx,
    const int* __restrict__ mask,
    float* __restrict__ out,
    int n)
{
    int wid   = threadIdx.x >> 5;
    int lane  = threadIdx.x & 31;
    int gwarp = blockIdx.x * (256 / 32) + wid;
    const int total_warps = NBLOCKS * (256 / 32);

    for (int node = gwarp; node < n; node += total_warps) {
        // ---- 16 int32 mask values as 4x int4 (uniform across warp) ----
        const int4* mp = reinterpret_cast<const int4*>(mask + (size_t)node * S);
        unsigned nz = 0;
#pragma unroll
        for (int q = 0; q < 4; q++) {
            int4 m = __ldg(mp + q);
            nz |= (unsigned)(m.x != 0) << (4 * q + 0);
            nz |= (unsigned)(m.y != 0) << (4 * q + 1);
            nz |= (unsigned)(m.z != 0) << (4 * q + 2);
            nz |= (unsigned)(m.w != 0) << (4 * q + 3);
        }
        int cnt = __popc(nz);

        // ---- 16 int32 indices as 4x int4 (uniform across warp) ----
        const int4* ip = reinterpret_cast<const int4*>(nidx + (size_t)node * S);
        int idx[S];
#pragma unroll
        for (int q = 0; q < 4; q++) {
            int4 v = __ldg(ip + q);
            idx[4 * q + 0] = v.x; idx[4 * q + 1] = v.y;
            idx[4 * q + 2] = v.z; idx[4 * q + 3] = v.w;
        }

        // ---- flat predicated gathers: @P LDG.128.CG, packed f32x2 ----
        unsigned long long aLo = 0ull, aHi = 0ull;   // bitwise 0 == (0.f, 0.f)
#pragma unroll
        for (int j = 0; j < S; j++) {
            if ((nz >> j) & 1u) {
                const float4* row =
                    reinterpret_cast<const float4*>(feat + (size_t)idx[j] * D) + lane;
                float4 v = __ldcg(row);
                unsigned long long lo, hi;
                asm("mov.b64 %0, {%1, %2};" : "=l"(lo) : "f"(v.x), "f"(v.y));
                asm("mov.b64 %0, {%1, %2};" : "=l"(hi) : "f"(v.z), "f"(v.w));
                aLo = addx2(aLo, lo);
                aHi = addx2(aHi, hi);
            }
        }

        // ---- scale by 1/count and store ----
        float inv = 1.0f / (float)(cnt > 0 ? cnt : 1);
        float x, y, z, w;
        asm("mov.b64 {%0, %1}, %2;" : "=f"(x), "=f"(y) : "l"(aLo));
        asm("mov.b64 {%0, %1}, %2;" : "=f"(z), "=f"(w) : "l"(aHi));
        float4 r = make_float4(x * inv, y * inv, z * inv, w * inv);
        __stcg(reinterpret_cast<float4*>(out) + (size_t)node * (D / 4) + lane, r);
    }
}

extern "C" void kernel_launch(void* const* d_in, const int* in_sizes, int n_in,
                              void* d_out, int out_size)
{
    const float* feat = (const float*)d_in[0];
    const int*   nidx = (const int*)d_in[1];
    const int*   mask = (const int*)d_in[2];
    float*       out  = (float*)d_out;

    int n = in_sizes[1] / S;              // 100000 nodes
    agg_kernel<<<NBLOCKS, 256>>>(feat, nidx, mask, out, n);
}

// round 16
// speedup vs baseline: 1.0705x; 1.0705x over previous
#include <cuda_runtime.h>
#include <cuda_fp16.h>
#include <cstdint>

// Aggregator: masked mean of sampled neighbor features.
//  d_in[0] features:      [N, 128] float32
//  d_in[1] neighbor_idx:  [N, 16]  int32
//  d_in[2] neighbor_mask: [N, 16]  int32 (0/1)
//  d_out   out:           [N, 128] float32
//
// The plateau at ~47us is the chip LTS (L2) byte cap: ~670MB of L2 traffic
// per call, dominated by 602MB of feature gathers. This version halves the
// gather bytes by converting the feature table to fp16 once per call into a
// __device__ scratch table (kernel 1), then gathering fp16 (kernel 2) with
// fp32 accumulation. fp16 error (~5e-4/elem, ~1.4e-4 after averaging) is
// well inside the 1e-3 threshold. Gather kernel keeps the champion
// structure: one warp/node, uniform int4 idx/mask loads, flat predicated
// gathers (now LDG.64.CG), STG.CG output.

#define S 16
#define D 128
#define MAXN 100000

__device__ __half g_feat16[(size_t)MAXN * D];   // 25.6 MB scratch (allowed)

// ---------------- kernel 1: fp32 -> fp16 table ----------------
__global__ __launch_bounds__(256) void cvt_kernel(const float* __restrict__ feat, int total4)
{
    int i = blockIdx.x * blockDim.x + threadIdx.x;
    if (i >= total4) return;
    float4 v = __ldcs(reinterpret_cast<const float4*>(feat) + i);  // evict-first: keep fp32 out of L2
    __half2 h0 = __floats2half2_rn(v.x, v.y);
    __half2 h1 = __floats2half2_rn(v.z, v.w);
    uint2 o;
    o.x = *reinterpret_cast<unsigned*>(&h0);
    o.y = *reinterpret_cast<unsigned*>(&h1);
    reinterpret_cast<uint2*>(g_feat16)[i] = o;
}

// ---------------- kernel 2: fp16 gather + fp32 mean ----------------
__global__ __launch_bounds__(256) void agg16_kernel(
    const int* __restrict__ nidx,
    const int* __restrict__ mask,
    float* __restrict__ out,
    int n)
{
    int warp = (int)((blockIdx.x * (unsigned)blockDim.x + threadIdx.x) >> 5);
    int lane = threadIdx.x & 31;
    if (warp >= n) return;

    // ---- 16 int32 mask values as 4x int4 (uniform across warp) ----
    const int4* mp = reinterpret_cast<const int4*>(mask + (size_t)warp * S);
    unsigned nz = 0;
#pragma unroll
    for (int q = 0; q < 4; q++) {
        int4 m = __ldg(mp + q);
        nz |= (unsigned)(m.x != 0) << (4 * q + 0);
        nz |= (unsigned)(m.y != 0) << (4 * q + 1);
        nz |= (unsigned)(m.z != 0) << (4 * q + 2);
        nz |= (unsigned)(m.w != 0) << (4 * q + 3);
    }
    int cnt = __popc(nz);

    // ---- 16 int32 indices as 4x int4 (uniform across warp) ----
    const int4* ip = reinterpret_cast<const int4*>(nidx + (size_t)warp * S);
    int idx[S];
#pragma unroll
    for (int q = 0; q < 4; q++) {
        int4 v = __ldg(ip + q);
        idx[4 * q + 0] = v.x; idx[4 * q + 1] = v.y;
        idx[4 * q + 2] = v.z; idx[4 * q + 3] = v.w;
    }

    // ---- flat predicated fp16 gathers: LDG.64.CG (256B/warp/row) ----
    float4 acc = make_float4(0.f, 0.f, 0.f, 0.f);
#pragma unroll
    for (int j = 0; j < S; j++) {
        if ((nz >> j) & 1u) {
            const uint2* row =
                reinterpret_cast<const uint2*>(g_feat16 + (size_t)idx[j] * D) + lane;
            uint2 v = __ldcg(row);                   // 4 halfs: cols [4l, 4l+4)
            __half2 h0 = *reinterpret_cast<__half2*>(&v.x);
            __half2 h1 = *reinterpret_cast<__half2*>(&v.y);
            float2 f0 = __half22float2(h0);
            float2 f1 = __half22float2(h1);
            acc.x += f0.x; acc.y += f0.y;
            acc.z += f1.x; acc.w += f1.y;
        }
    }

    // ---- scale by 1/count and store ----
    float inv = 1.0f / (float)(cnt > 0 ? cnt : 1);
    float4 r = make_float4(acc.x * inv, acc.y * inv, acc.z * inv, acc.w * inv);
    __stcg(reinterpret_cast<float4*>(out) + (size_t)warp * (D / 4) + lane, r);
}

// ---------------- fallback: proven fp32 champion (n > MAXN) ----------------
__device__ __forceinline__ unsigned long long addx2(unsigned long long a, unsigned long long b) {
    unsigned long long r;
    asm("add.rn.f32x2 %0, %1, %2;" : "=l"(r) : "l"(a), "l"(b));
    return r;
}

__global__ __launch_bounds__(256) void agg32_kernel(
    const float* __restrict__ feat,
    const int* __restrict__ nidx,
    const int* __restrict__ mask,
    float* __restrict__ out,
    int n)
{
    int warp = (int)((blockIdx.x * (unsigned)blockDim.x + threadIdx.x) >> 5);
    int lane = threadIdx.x & 31;
    if (warp >= n) return;

    const int4* mp = reinterpret_cast<const int4*>(mask + (size_t)warp * S);
    unsigned nz = 0;
#pragma unroll
    for (int q = 0; q < 4; q++) {
        int4 m = __ldg(mp + q);
        nz |= (unsigned)(m.x != 0) << (4 * q + 0);
        nz |= (unsigned)(m.y != 0) << (4 * q + 1);
        nz |= (unsigned)(m.z != 0) << (4 * q + 2);
        nz |= (unsigned)(m.w != 0) << (4 * q + 3);
    }
    int cnt = __popc(nz);

    const int4* ip = reinterpret_cast<const int4*>(nidx + (size_t)warp * S);
    int idx[S];
#pragma unroll
    for (int q = 0; q < 4; q++) {
        int4 v = __ldg(ip + q);
        idx[4 * q + 0] = v.x; idx[4 * q + 1] = v.y;
        idx[4 * q + 2] = v.z; idx[4 * q + 3] = v.w;
    }

    unsigned long long aLo = 0ull, aHi = 0ull;
#pragma unroll
    for (int j = 0; j < S; j++) {
        if ((nz >> j) & 1u) {
            const float4* row =
                reinterpret_cast<const float4*>(feat + (size_t)idx[j] * D) + lane;
            float4 v = __ldcg(row);
            unsigned long long lo, hi;
            asm("mov.b64 %0, {%1, %2};" : "=l"(lo) : "f"(v.x), "f"(v.y));
            asm("mov.b64 %0, {%1, %2};" : "=l"(hi) : "f"(v.z), "f"(v.w));
            aLo = addx2(aLo, lo);
            aHi = addx2(aHi, hi);
        }
    }

    float inv = 1.0f / (float)(cnt > 0 ? cnt : 1);
    float x, y, z, w;
    asm("mov.b64 {%0, %1}, %2;" : "=f"(x), "=f"(y) : "l"(aLo));
    asm("mov.b64 {%0, %1}, %2;" : "=f"(z), "=f"(w) : "l"(aHi));
    float4 r = make_float4(x * inv, y * inv, z * inv, w * inv);
    __stcg(reinterpret_cast<float4*>(out) + (size_t)warp * (D / 4) + lane, r);
}

extern "C" void kernel_launch(void* const* d_in, const int* in_sizes, int n_in,
                              void* d_out, int out_size)
{
    const float* feat = (const float*)d_in[0];
    const int*   nidx = (const int*)d_in[1];
    const int*   mask = (const int*)d_in[2];
    float*       out  = (float*)d_out;

    int n = in_sizes[1] / S;                       // 100000 nodes
    int warps_per_block = 256 / 32;                // 8
    int blocks = (n + warps_per_block - 1) / warps_per_block;

    if (n <= MAXN && in_sizes[0] == n * D) {
        int total4 = n * (D / 4);                  // float4 count
        int cblocks = (total4 + 255) / 256;
        cvt_kernel<<<cblocks, 256>>>(feat, total4);
        agg16_kernel<<<blocks, 256>>>(nidx, mask, out, n);
    } else {
        agg32_kernel<<<blocks, 256>>>(feat, nidx, mask, out, n);
    }
}

// round 17
// speedup vs baseline: 1.1659x; 1.0891x over previous
#include <cuda_runtime.h>
#include <cuda_fp16.h>
#include <cstdint>

// Aggregator: masked mean of sampled neighbor features.
//  d_in[0] features:      [N, 128] float32
//  d_in[1] neighbor_idx:  [N, 16]  int32
//  d_in[2] neighbor_mask: [N, 16]  int32 (0/1)
//  d_out   out:           [N, 128] float32
//
// Two-kernel scheme: (1) fp32 -> fp16 table into __device__ scratch,
// (2) fp16 gather + mean. R16 showed the fp16 gather is ISSUE-bound on
// per-gather convert arithmetic (fma 44%, issue 68%). This version
// accumulates each group of 4 samples in fp16 via HADD2 (2 ops/gather
// instead of 4 cvt + 4 add), upconverting group sums to fp32 once per
// group. Precision: ~3e-4 added RMS after /cnt, well under 1e-3.

#define S 16
#define D 128
#define MAXN 100000

__device__ __half g_feat16[(size_t)MAXN * D];   // 25.6 MB scratch

// ---------------- kernel 1: fp32 -> fp16 table ----------------
__global__ __launch_bounds__(256) void cvt_kernel(const float* __restrict__ feat, int total4)
{
    int i = blockIdx.x * blockDim.x + threadIdx.x;
    if (i >= total4) return;
    float4 v = __ldcs(reinterpret_cast<const float4*>(feat) + i);  // evict-first
    __half2 h0 = __floats2half2_rn(v.x, v.y);
    __half2 h1 = __floats2half2_rn(v.z, v.w);
    uint2 o;
    o.x = *reinterpret_cast<unsigned*>(&h0);
    o.y = *reinterpret_cast<unsigned*>(&h1);
    reinterpret_cast<uint2*>(g_feat16)[i] = o;
}

// ---------------- kernel 2: fp16 gather, HADD2 group accumulation ----------------
__global__ __launch_bounds__(256) void agg16_kernel(
    const int* __restrict__ nidx,
    const int* __restrict__ mask,
    float* __restrict__ out,
    int n)
{
    int warp = (int)((blockIdx.x * (unsigned)blockDim.x + threadIdx.x) >> 5);
    int lane = threadIdx.x & 31;
    if (warp >= n) return;

    // ---- 16 int32 mask values as 4x int4 (uniform across warp) ----
    const int4* mp = reinterpret_cast<const int4*>(mask + (size_t)warp * S);
    unsigned nz = 0;
#pragma unroll
    for (int q = 0; q < 4; q++) {
        int4 m = __ldg(mp + q);
        nz |= (unsigned)(m.x != 0) << (4 * q + 0);
        nz |= (unsigned)(m.y != 0) << (4 * q + 1);
        nz |= (unsigned)(m.z != 0) << (4 * q + 2);
        nz |= (unsigned)(m.w != 0) << (4 * q + 3);
    }
    int cnt = __popc(nz);

    // ---- 16 int32 indices as 4x int4 (uniform across warp) ----
    const int4* ip = reinterpret_cast<const int4*>(nidx + (size_t)warp * S);
    int idx[S];
#pragma unroll
    for (int q = 0; q < 4; q++) {
        int4 v = __ldg(ip + q);
        idx[4 * q + 0] = v.x; idx[4 * q + 1] = v.y;
        idx[4 * q + 2] = v.z; idx[4 * q + 3] = v.w;
    }

    // ---- 4 groups of 4: fp16 HADD2 accumulation, fp32 group upconvert ----
    float4 acc = make_float4(0.f, 0.f, 0.f, 0.f);
    const __half2 hz = __float2half2_rn(0.f);
#pragma unroll
    for (int g = 0; g < 4; g++) {
        __half2 s0 = hz, s1 = hz;
#pragma unroll
        for (int u = 0; u < 4; u++) {
            int j = g * 4 + u;
            if ((nz >> j) & 1u) {
                const uint2* row =
                    reinterpret_cast<const uint2*>(g_feat16 + (size_t)idx[j] * D) + lane;
                uint2 v = __ldcg(row);                 // 4 halfs: cols [4l, 4l+4)
                s0 = __hadd2(s0, *reinterpret_cast<__half2*>(&v.x));
                s1 = __hadd2(s1, *reinterpret_cast<__half2*>(&v.y));
            }
        }
        float2 f0 = __half22float2(s0);
        float2 f1 = __half22float2(s1);
        acc.x += f0.x; acc.y += f0.y;
        acc.z += f1.x; acc.w += f1.y;
    }

    // ---- scale by 1/count and store ----
    float inv = 1.0f / (float)(cnt > 0 ? cnt : 1);
    float4 r = make_float4(acc.x * inv, acc.y * inv, acc.z * inv, acc.w * inv);
    __stcg(reinterpret_cast<float4*>(out) + (size_t)warp * (D / 4) + lane, r);
}

// ---------------- fallback: proven fp32 champion (n > MAXN) ----------------
__device__ __forceinline__ unsigned long long addx2(unsigned long long a, unsigned long long b) {
    unsigned long long r;
    asm("add.rn.f32x2 %0, %1, %2;" : "=l"(r) : "l"(a), "l"(b));
    return r;
}

__global__ __launch_bounds__(256) void agg32_kernel(
    const float* __restrict__ feat,
    const int* __restrict__ nidx,
    const int* __restrict__ mask,
    float* __restrict__ out,
    int n)
{
    int warp = (int)((blockIdx.x * (unsigned)blockDim.x + threadIdx.x) >> 5);
    int lane = threadIdx.x & 31;
    if (warp >= n) return;

    const int4* mp = reinterpret_cast<const int4*>(mask + (size_t)warp * S);
    unsigned nz = 0;
#pragma unroll
    for (int q = 0; q < 4; q++) {
        int4 m = __ldg(mp + q);
        nz |= (unsigned)(m.x != 0) << (4 * q + 0);
        nz |= (unsigned)(m.y != 0) << (4 * q + 1);
        nz |= (unsigned)(m.z != 0) << (4 * q + 2);
        nz |= (unsigned)(m.w != 0) << (4 * q + 3);
    }
    int cnt = __popc(nz);

    const int4* ip = reinterpret_cast<const int4*>(nidx + (size_t)warp * S);
    int idx[S];
#pragma unroll
    for (int q = 0; q < 4; q++) {
        int4 v = __ldg(ip + q);
        idx[4 * q + 0] = v.x; idx[4 * q + 1] = v.y;
        idx[4 * q + 2] = v.z; idx[4 * q + 3] = v.w;
    }

    unsigned long long aLo = 0ull, aHi = 0ull;
#pragma unroll
    for (int j = 0; j < S; j++) {
        if ((nz >> j) & 1u) {
            const float4* row =
                reinterpret_cast<const float4*>(feat + (size_t)idx[j] * D) + lane;
            float4 v = __ldcg(row);
            unsigned long long lo, hi;
            asm("mov.b64 %0, {%1, %2};" : "=l"(lo) : "f"(v.x), "f"(v.y));
            asm("mov.b64 %0, {%1, %2};" : "=l"(hi) : "f"(v.z), "f"(v.w));
            aLo = addx2(aLo, lo);
            aHi = addx2(aHi, hi);
        }
    }

    float inv = 1.0f / (float)(cnt > 0 ? cnt : 1);
    float x, y, z, w;
    asm("mov.b64 {%0, %1}, %2;" : "=f"(x), "=f"(y) : "l"(aLo));
    asm("mov.b64 {%0, %1}, %2;" : "=f"(z), "=f"(w) : "l"(aHi));
    float4 r = make_float4(x * inv, y * inv, z * inv, w * inv);
    __stcg(reinterpret_cast<float4*>(out) + (size_t)warp * (D / 4) + lane, r);
}

extern "C" void kernel_launch(void* const* d_in, const int* in_sizes, int n_in,
                              void* d_out, int out_size)
{
    const float* feat = (const float*)d_in[0];
    const int*   nidx = (const int*)d_in[1];
    const int*   mask = (const int*)d_in[2];
    float*       out  = (float*)d_out;

    int n = in_sizes[1] / S;                       // 100000 nodes
    int warps_per_block = 256 / 32;                // 8
    int blocks = (n + warps_per_block - 1) / warps_per_block;

    if (n <= MAXN && in_sizes[0] == n * D) {
        int total4 = n * (D / 4);                  // float4 count
        int cblocks = (total4 + 255) / 256;
        cvt_kernel<<<cblocks, 256>>>(feat, total4);
        agg16_kernel<<<blocks, 256>>>(nidx, mask, out, n);
    } else {
        agg32_kernel<<<blocks, 256>>>(feat, nidx, mask, out, n);
    }
}